// round 15
// baseline (speedup 1.0000x reference)
#include <cuda_runtime.h>
#include <math.h>

#define DD 96
#define NPART 48
#define PITCH 97
#define NTHREADS 512

__device__ double g_G[DD * DD];
__device__ double g_pk[NPART];
__device__ unsigned int g_count = 0;

// Fast fp64 reciprocal: f32 rcp seed + 2 fp64 Newton steps (~1e-14 rel).
__device__ __forceinline__ double fast_recip(double p) {
    float pf = (float)p;
    float rf;
    asm("rcp.approx.f32 %0, %1;" : "=f"(rf) : "f"(pf));
    double r = (double)rf;
    r = r * __fma_rn(-p, r, 2.0);
    r = r * __fma_rn(-p, r, 2.0);
    return r;
}

// ---------------------------------------------------------------------------
// G = I - P P^T  (96 blocks x 96 threads; measured-best variant).
// ---------------------------------------------------------------------------
__global__ void build_G_kernel(const float* __restrict__ P) {
    __shared__ float Pt[NPART][DD];  // Pt[t][i] = P[i*NPART+t]
    const int i = blockIdx.x;
    const int tid = threadIdx.x;  // 96

    for (int idx = tid; idx < DD * NPART; idx += DD) {
        int r = idx / NPART;
        int t = idx - r * NPART;
        Pt[t][r] = P[idx];
    }
    __syncthreads();

    const int j = tid;
    double a0 = 0.0, a1 = 0.0, a2 = 0.0, a3 = 0.0;
#pragma unroll
    for (int t = 0; t < NPART; t += 4) {
        a0 = __fma_rn((double)Pt[t][i],     (double)Pt[t][j],     a0);
        a1 = __fma_rn((double)Pt[t + 1][i], (double)Pt[t + 1][j], a1);
        a2 = __fma_rn((double)Pt[t + 2][i], (double)Pt[t + 2][j], a2);
        a3 = __fma_rn((double)Pt[t + 3][i], (double)Pt[t + 3][j], a3);
    }
    g_G[i * DD + j] = ((i == j) ? 1.0 : 0.0) - ((a0 + a1) + (a2 + a3));
}

// ---------------------------------------------------------------------------
// Per-k unpivoted symmetric elimination, RANK-2 steps (one barrier retires two
// pivots), 512 threads / 16 warps for latency hiding (ncu r14: occ 12.5%,
// issue 11.7% at 256 threads -> issue-starved).
// Warps 1..15: rank-2 trailing update of rows >= i0+4 (stride 15).
// Warp 0: prepares the next pivot pair (rows i0+2, i0+3).
// Factors come from pivot-row values (symmetry of the iterate).
// Ends with fused "last block computes prob_sample" reduction.
// ---------------------------------------------------------------------------
__global__ void __launch_bounds__(NTHREADS, 1)
lu_probs_kernel(const int* __restrict__ occ, float* __restrict__ out) {
    extern __shared__ double A_[];     // [DD][PITCH] dynamic
    __shared__ double U[2][2][DD];     // pair-buffered pivot rows
    __shared__ double s_inv[2][2];
    __shared__ double s_piv[DD];
    __shared__ double sc[2][DD];
    __shared__ int s_occ[NPART];
    __shared__ int s_last;

    const int k = blockIdx.x;
    const int m = DD - NPART + k + 1;   // 49 + k
    const int tid = threadIdx.x;        // 512
    const int tx = tid & 31;
    const int ty = tid >> 5;            // 0..15

    if (tid < NPART) s_occ[tid] = occ[tid];

    // Load leading m x m block of G.
    for (int r = ty; r < m; r += 16)
        for (int c = tx; c < m; c += 32)
            A_[r * PITCH + c] = g_G[r * DD + c];
    __syncthreads();
    if (tid < k) {                      // distinct positions -> race-free
        int p = s_occ[tid];
        if (p < m) A_[p * PITCH + p] -= 1.0;
    }
    __syncthreads();

    // Init: pivot rows 0 and 1.
    if (tid < m) U[0][0][tid] = A_[tid];
    if (tid == 0) {
        double p0 = A_[0];
        s_piv[0] = p0;
        s_inv[0][0] = fast_recip(p0);
    }
    __syncthreads();
    if (ty == 0) {
        const double inv0 = s_inv[0][0];
        const double* __restrict__ u0 = U[0][0];
        const double l1 = u0[1] * inv0;
        double pcap = 0.0;
        for (int c = 1 + tx; c < m; c += 32) {
            double v = __fma_rn(-l1, u0[c], A_[PITCH + c]);
            U[0][1][c] = v;
            if (c == 1) pcap = v;       // lane 0 only
        }
        if (tx == 0) {
            s_piv[1] = pcap;
            s_inv[0][1] = fast_recip(pcap);
        }
    }
    __syncthreads();

    for (int i0 = 0; i0 + 2 < m; i0 += 2) {
        const int pb = (i0 >> 1) & 1;
        const double inv0 = s_inv[pb][0];
        const double inv1 = s_inv[pb][1];
        const double* __restrict__ u0 = U[pb][0];
        const double* __restrict__ u1 = U[pb][1];
        double* __restrict__ v2 = U[pb ^ 1][0];
        double* __restrict__ v3 = U[pb ^ 1][1];
        const int r2 = i0 + 2, r3 = i0 + 3;

        if (ty == 0) {
            // Finalize pivot row r2 (rank-2 update), capture pivot.
            const double la = u0[r2] * inv0;
            const double lb = u1[r2] * inv1;
            const double* __restrict__ arow2 = &A_[r2 * PITCH];
            double pcap2 = 0.0;
            for (int c = r2 + tx; c < m; c += 32) {
                double v = arow2[c];
                v = __fma_rn(-la, u0[c], v);
                v = __fma_rn(-lb, u1[c], v);
                v2[c] = v;
                if (c == r2) pcap2 = v;
            }
            const double p2 = __shfl_sync(0xFFFFFFFFu, pcap2, 0);
            const double inv2 = fast_recip(p2);
            if (tx == 0) {
                s_piv[r2] = p2;
                s_inv[pb ^ 1][0] = inv2;
            }
            __syncwarp();
            if (r3 < m) {
                // Finalize pivot row r3: rank-2 + elimination vs row r2.
                const double lc = u0[r3] * inv0;
                const double ld = u1[r3] * inv1;
                const double f2 = v2[r3] * inv2;
                const double* __restrict__ arow3 = &A_[r3 * PITCH];
                double pcap3 = 0.0;
                for (int c = r3 + tx; c < m; c += 32) {
                    double v = arow3[c];
                    v = __fma_rn(-lc, u0[c], v);
                    v = __fma_rn(-ld, u1[c], v);
                    v = __fma_rn(-f2, v2[c], v);
                    v3[c] = v;
                    if (c == r3) pcap3 = v;
                }
                if (tx == 0) {
                    s_piv[r3] = pcap3;
                    s_inv[pb ^ 1][1] = fast_recip(pcap3);
                }
            }
        } else {
            // Rank-2 trailing update of rows i0+4 .. m-1 (stride 15).
            for (int r = i0 + 3 + ty; r < m; r += 15) {
                const double la = u0[r] * inv0;
                const double lb = u1[r] * inv1;
                double* __restrict__ arow = &A_[r * PITCH];
                for (int c = r2 + tx; c < m; c += 32) {
                    double v = arow[c];
                    v = __fma_rn(-la, u0[c], v);
                    v = __fma_rn(-lb, u1[c], v);
                    arow[c] = v;
                }
            }
        }
        __syncthreads();
    }

    const int xmin = (k == 0) ? 0 : s_occ[k - 1] + 1;

    // Inclusive prefix product of pivots masked to [xmin, m).
    if (tid < DD) sc[0][tid] = (tid >= xmin && tid < m) ? s_piv[tid] : 1.0;
    __syncthreads();
    int src = 0;
    for (int off = 1; off < DD; off <<= 1) {
        if (tid < DD) {
            double v = sc[src][tid];
            if (tid >= off) v *= sc[src][tid - off];
            sc[src ^ 1][tid] = v;
        }
        __syncthreads();
        src ^= 1;
    }

    if (tid < DD) {
        const int x = tid;
        double pr = 0.0;
        if (x >= xmin && x < m) {
            const double S = (x == xmin) ? 1.0 : sc[src][x - 1];
            pr = -S * (s_piv[x] - 1.0);
            if (!(fabs(pr) > 1e-15)) pr = 0.0;
        }
        out[k * DD + x] = (float)pr;
        if (x == s_occ[k]) g_pk[k] = pr;
    }

    // ---- fused prob_sample: last block to finish multiplies g_pk ----
    __syncthreads();
    if (tid == 0) {
        __threadfence();
        unsigned int n = atomicAdd(&g_count, 1u);
        s_last = (n == NPART - 1) ? 1 : 0;
    }
    __syncthreads();
    if (s_last) {
        if (tid < 32) {
            volatile double* vp = g_pk;
            double v = vp[tid];
            if (tid < 16) v *= vp[32 + tid];
#pragma unroll
            for (int off = 16; off > 0; off >>= 1)
                v *= __shfl_xor_sync(0xFFFFFFFFu, v, off);
            if (tid == 0) {
                out[NPART * DD] = (float)v;
                g_count = 0;  // reset for next graph replay
            }
        }
    }
}

extern "C" void kernel_launch(void* const* d_in, const int* in_sizes, int n_in,
                              void* d_out, int out_size) {
    const float* P;
    const int* occ;
    if (in_sizes[0] == DD * NPART) {
        P = (const float*)d_in[0];
        occ = (const int*)d_in[1];
    } else {
        P = (const float*)d_in[1];
        occ = (const int*)d_in[0];
    }
    float* out = (float*)d_out;

    const int smem = DD * PITCH * (int)sizeof(double);  // 74496 B
    cudaFuncSetAttribute(lu_probs_kernel,
                         cudaFuncAttributeMaxDynamicSharedMemorySize, smem);

    build_G_kernel<<<DD, DD>>>(P);
    lu_probs_kernel<<<NPART, NTHREADS, smem>>>(occ, out);
}

// round 16
// speedup vs baseline: 3.8814x; 3.8814x over previous
#include <cuda_runtime.h>
#include <math.h>

#define DD 96
#define NPART 48
#define PITCH 97
#define NTHREADS 512

__device__ float g_G[DD * DD];
__device__ double g_pk[NPART];
__device__ unsigned int g_count = 0;

// fp32 reciprocal: rcp.approx seed + 1 Newton step (~2^-22 rel).
__device__ __forceinline__ float fast_recip_f(float p) {
    float r;
    asm("rcp.approx.f32 %0, %1;" : "=f"(r) : "f"(p));
    r = r * __fmaf_rn(-p, r, 2.0f);
    return r;
}

// ---------------------------------------------------------------------------
// G = I - P P^T in fp32 (96 blocks x 96 threads; measured-best shape).
// ---------------------------------------------------------------------------
__global__ void build_G_kernel(const float* __restrict__ P) {
    __shared__ float Pt[NPART][DD];  // Pt[t][i] = P[i*NPART+t]
    const int i = blockIdx.x;
    const int tid = threadIdx.x;  // 96

    for (int idx = tid; idx < DD * NPART; idx += DD) {
        int r = idx / NPART;
        int t = idx - r * NPART;
        Pt[t][r] = P[idx];
    }
    __syncthreads();

    const int j = tid;
    float a0 = 0.f, a1 = 0.f, a2 = 0.f, a3 = 0.f;
#pragma unroll
    for (int t = 0; t < NPART; t += 4) {
        a0 = __fmaf_rn(Pt[t][i],     Pt[t][j],     a0);
        a1 = __fmaf_rn(Pt[t + 1][i], Pt[t + 1][j], a1);
        a2 = __fmaf_rn(Pt[t + 2][i], Pt[t + 2][j], a2);
        a3 = __fmaf_rn(Pt[t + 3][i], Pt[t + 3][j], a3);
    }
    g_G[i * DD + j] = ((i == j) ? 1.0f : 0.0f) - ((a0 + a1) + (a2 + a3));
}

// ---------------------------------------------------------------------------
// Per-k unpivoted symmetric elimination in fp32, RANK-2 steps (one barrier
// retires two pivots).  Matrix + pivot rows in fp32 (FFMA lat 4 vs DFMA 47
// -> per-step critical chain ~2.5x shorter at the idle clocks this kernel
// runs at).  Pivots accumulated into the prefix product in fp64.
// Warp 0 prepares the next pivot pair; warps 1..15 rank-2 trailing update.
// Ends with fused "last block computes prob_sample" reduction (fp64).
// ---------------------------------------------------------------------------
__global__ void __launch_bounds__(NTHREADS, 1)
lu_probs_kernel(const int* __restrict__ occ, float* __restrict__ out) {
    extern __shared__ float A_[];      // [DD][PITCH] dynamic, fp32
    __shared__ float U[2][2][DD];      // pair-buffered pivot rows
    __shared__ float s_inv[2][2];
    __shared__ float s_piv[DD];
    __shared__ double sc[2][DD];
    __shared__ int s_occ[NPART];
    __shared__ int s_last;

    const int k = blockIdx.x;
    const int m = DD - NPART + k + 1;   // 49 + k
    const int tid = threadIdx.x;        // 512
    const int tx = tid & 31;
    const int ty = tid >> 5;            // 0..15

    if (tid < NPART) s_occ[tid] = occ[tid];

    // Load leading m x m block of G.
    for (int r = ty; r < m; r += 16)
        for (int c = tx; c < m; c += 32)
            A_[r * PITCH + c] = g_G[r * DD + c];
    __syncthreads();
    if (tid < k) {                      // distinct positions -> race-free
        int p = s_occ[tid];
        if (p < m) A_[p * PITCH + p] -= 1.0f;
    }
    __syncthreads();

    // Init: pivot rows 0 and 1.
    if (tid < m) U[0][0][tid] = A_[tid];
    if (tid == 0) {
        float p0 = A_[0];
        s_piv[0] = p0;
        s_inv[0][0] = fast_recip_f(p0);
    }
    __syncthreads();
    if (ty == 0) {
        const float inv0 = s_inv[0][0];
        const float* __restrict__ u0 = U[0][0];
        const float l1 = u0[1] * inv0;
        float pcap = 0.f;
        for (int c = 1 + tx; c < m; c += 32) {
            float v = __fmaf_rn(-l1, u0[c], A_[PITCH + c]);
            U[0][1][c] = v;
            if (c == 1) pcap = v;       // lane 0 only
        }
        if (tx == 0) {
            s_piv[1] = pcap;
            s_inv[0][1] = fast_recip_f(pcap);
        }
    }
    __syncthreads();

    for (int i0 = 0; i0 + 2 < m; i0 += 2) {
        const int pb = (i0 >> 1) & 1;
        const float inv0 = s_inv[pb][0];
        const float inv1 = s_inv[pb][1];
        const float* __restrict__ u0 = U[pb][0];
        const float* __restrict__ u1 = U[pb][1];
        float* __restrict__ v2 = U[pb ^ 1][0];
        float* __restrict__ v3 = U[pb ^ 1][1];
        const int r2 = i0 + 2, r3 = i0 + 3;

        if (ty == 0) {
            // Finalize pivot row r2 (rank-2 update), capture pivot.
            const float la = u0[r2] * inv0;
            const float lb = u1[r2] * inv1;
            const float* __restrict__ arow2 = &A_[r2 * PITCH];
            float pcap2 = 0.f;
            for (int c = r2 + tx; c < m; c += 32) {
                float v = arow2[c];
                v = __fmaf_rn(-la, u0[c], v);
                v = __fmaf_rn(-lb, u1[c], v);
                v2[c] = v;
                if (c == r2) pcap2 = v;
            }
            const float p2 = __shfl_sync(0xFFFFFFFFu, pcap2, 0);
            const float inv2 = fast_recip_f(p2);
            if (tx == 0) {
                s_piv[r2] = p2;
                s_inv[pb ^ 1][0] = inv2;
            }
            __syncwarp();
            if (r3 < m) {
                // Finalize pivot row r3: rank-2 + elimination vs row r2.
                const float lc = u0[r3] * inv0;
                const float ld = u1[r3] * inv1;
                const float f2 = v2[r3] * inv2;
                const float* __restrict__ arow3 = &A_[r3 * PITCH];
                float pcap3 = 0.f;
                for (int c = r3 + tx; c < m; c += 32) {
                    float v = arow3[c];
                    v = __fmaf_rn(-lc, u0[c], v);
                    v = __fmaf_rn(-ld, u1[c], v);
                    v = __fmaf_rn(-f2, v2[c], v);
                    v3[c] = v;
                    if (c == r3) pcap3 = v;
                }
                if (tx == 0) {
                    s_piv[r3] = pcap3;
                    s_inv[pb ^ 1][1] = fast_recip_f(pcap3);
                }
            }
        } else {
            // Rank-2 trailing update of rows i0+4 .. m-1 (stride 15).
            for (int r = i0 + 3 + ty; r < m; r += 15) {
                const float la = u0[r] * inv0;
                const float lb = u1[r] * inv1;
                float* __restrict__ arow = &A_[r * PITCH];
                for (int c = r2 + tx; c < m; c += 32) {
                    float v = arow[c];
                    v = __fmaf_rn(-la, u0[c], v);
                    v = __fmaf_rn(-lb, u1[c], v);
                    arow[c] = v;
                }
            }
        }
        __syncthreads();
    }

    const int xmin = (k == 0) ? 0 : s_occ[k - 1] + 1;

    // Inclusive prefix product of pivots masked to [xmin, m) — in fp64.
    if (tid < DD)
        sc[0][tid] = (tid >= xmin && tid < m) ? (double)s_piv[tid] : 1.0;
    __syncthreads();
    int src = 0;
    for (int off = 1; off < DD; off <<= 1) {
        if (tid < DD) {
            double v = sc[src][tid];
            if (tid >= off) v *= sc[src][tid - off];
            sc[src ^ 1][tid] = v;
        }
        __syncthreads();
        src ^= 1;
    }

    if (tid < DD) {
        const int x = tid;
        double pr = 0.0;
        if (x >= xmin && x < m) {
            const double S = (x == xmin) ? 1.0 : sc[src][x - 1];
            pr = -S * ((double)s_piv[x] - 1.0);
            if (!(fabs(pr) > 1e-15)) pr = 0.0;
        }
        out[k * DD + x] = (float)pr;
        if (x == s_occ[k]) g_pk[k] = pr;
    }

    // ---- fused prob_sample: last block to finish multiplies g_pk ----
    __syncthreads();
    if (tid == 0) {
        __threadfence();
        unsigned int n = atomicAdd(&g_count, 1u);
        s_last = (n == NPART - 1) ? 1 : 0;
    }
    __syncthreads();
    if (s_last) {
        if (tid < 32) {
            volatile double* vp = g_pk;
            double v = vp[tid];
            if (tid < 16) v *= vp[32 + tid];
#pragma unroll
            for (int off = 16; off > 0; off >>= 1)
                v *= __shfl_xor_sync(0xFFFFFFFFu, v, off);
            if (tid == 0) {
                out[NPART * DD] = (float)v;
                g_count = 0;  // reset for next graph replay
            }
        }
    }
}

extern "C" void kernel_launch(void* const* d_in, const int* in_sizes, int n_in,
                              void* d_out, int out_size) {
    const float* P;
    const int* occ;
    if (in_sizes[0] == DD * NPART) {
        P = (const float*)d_in[0];
        occ = (const int*)d_in[1];
    } else {
        P = (const float*)d_in[1];
        occ = (const int*)d_in[0];
    }
    float* out = (float*)d_out;

    const int smem = DD * PITCH * (int)sizeof(float);  // 37248 B
    cudaFuncSetAttribute(lu_probs_kernel,
                         cudaFuncAttributeMaxDynamicSharedMemorySize, smem);

    build_G_kernel<<<DD, DD>>>(P);
    lu_probs_kernel<<<NPART, NTHREADS, smem>>>(occ, out);
}